// round 8
// baseline (speedup 1.0000x reference)
#include <cuda_runtime.h>

// GrassmannNN: SITE=8, DIM=16, D=32, B=8192.
// Single fused kernel, three phases via device-side flag pipeline:
//   A (blocks 0..224):  build 28 16x16 layer matrices M + head vectors h
//   B (blocks 225..256): forward all 256 bit-patterns (1 warp each) -> table
//   C (blocks 257..512): per-row gather of 64-float pattern outputs
// 513 blocks co-resident at launch_bounds(256,4): 148*4=592 >= 513 -> no
// deadlock. Spin flags are fanned out (8 lines for C) and polled with
// backoff so the flag lines don't saturate an LTS slice.

#define NPAT 256

__device__ float g_M[7 * 2 * 2 * 256];          // [l][bit][s][i][k], sign folded
__device__ float g_h[32];                       // tanh(head) per bit
__device__ __align__(16) float g_T[NPAT * 64];  // pattern output table
__device__ int g_doneA;                         // zero-initialized
__device__ int g_doneB;
__device__ int g_doneC;
__device__ int g_flagB[8 * 32];                 // padded: one flag per 128B line

__device__ __forceinline__ int ld_acq(const int* p) {
    int v;
    asm volatile("ld.acquire.gpu.b32 %0, [%1];" : "=r"(v) : "l"(p));
    return v;
}

__global__ void __launch_bounds__(256, 4)
fused_kernel(const int* __restrict__ data,       // (8192, 8)
             const float* __restrict__ emb,      // (8, 2, 16)
             const float* __restrict__ head_w,   // (32, 32)
             const float* __restrict__ body_w,   // (7, 32, 32, 32)
             float4* __restrict__ out)           // (8192, 2, 32) as float4
{
    __shared__ __align__(16) float sh[1024];
    __shared__ int shp[32];
    const int b = blockIdx.x;
    const int t = threadIdx.x;

    if (b < 224) {
        // ---- Phase A: one (l, ig) slab per block -------------------------
        const int l = b >> 5, ig = b & 31;
        reinterpret_cast<float4*>(sh)[t] =
            reinterpret_cast<const float4*>(body_w + (size_t)(l * 32 + ig) * 1024)[t];
        __syncthreads();
        if (t < 32) {
            const int bit = t >> 4, k = t & 15;
            const int s1 = ig >> 4, i = ig & 15;
            const int s = bit ? (1 - s1) : s1;
            const float* e = emb + ((l + 1) * 2 + bit) * 16;
            float acc = 0.f;
#pragma unroll
            for (int j = 0; j < 16; ++j)
                acc = fmaf(e[j], sh[(bit * 16 + j) * 32 + s * 16 + k], acc);
            if (bit == 1 && s == 0) acc = -acc;
            g_M[(((l * 2 + bit) * 2 + s) * 16 + i) * 16 + k] = acc;
        }
        __threadfence();
        __syncthreads();
        if (t == 0) atomicAdd(&g_doneA, 1);      // no return use -> RED

    } else if (b == 224) {
        // ---- Phase A: head vectors ---------------------------------------
        if (t < 32) {
            const int bit = t >> 4, j = t & 15;
            const float* e = emb + bit * 16;
            float acc = 0.f;
#pragma unroll
            for (int k = 0; k < 16; ++k)
                acc = fmaf(e[k], head_w[(bit * 16 + k) * 32 + bit * 16 + j], acc);
            g_h[bit * 16 + j] = tanhf(acc);
        }
        __threadfence();
        __syncthreads();
        if (t == 0) atomicAdd(&g_doneA, 1);

    } else if (b < 257) {
        // ---- Phase B: 8 pattern warps per block --------------------------
        if (t == 0)
            while (ld_acq(&g_doneA) < 225) { /* 32 pollers total: cheap */ }
        __syncthreads();

        const int lane = t & 31;
        const int p = (b - 225) * 8 + (t >> 5);
        const int s = lane >> 4, k = lane & 15;
        const int bit0 = p & 1;
        float u = (s == bit0) ? g_h[bit0 * 16 + k] : 0.f;

        // layer-0 coefficient load (only exposed L2 latency in the chain)
        float m[16];
        {
            const int bit = (p >> 1) & 1;
            const float* Mp = g_M + ((0 * 2 + bit) * 2 + s) * 256 + k;
#pragma unroll
            for (int i = 0; i < 16; ++i) m[i] = Mp[i * 16];
        }
#pragma unroll
        for (int l = 0; l < 7; ++l) {
            // prefetch next layer while computing this one
            float m2[16];
            if (l < 6) {
                const int bitn = (p >> (l + 2)) & 1;
                const float* Mn = g_M + (((l + 1) * 2 + bitn) * 2 + s) * 256 + k;
#pragma unroll
                for (int i = 0; i < 16; ++i) m2[i] = Mn[i * 16];
            }
            const int bit = (p >> (l + 1)) & 1;
            const int src = (bit ? (1 - s) : s) << 4;
            float acc = 0.f;
#pragma unroll
            for (int i = 0; i < 16; ++i)
                acc = fmaf(__shfl_sync(0xffffffffu, u, src + i), m[i], acc);
            u = tanhf(acc);
#pragma unroll
            for (int i = 0; i < 16; ++i) m[i] = m2[i];
        }

        float* o = g_T + p * 64;
        o[48 * s + k] = u;           // live sector
        o[16 + 16 * s + k] = 0.f;    // structurally-zero sector
        __threadfence();
        __syncthreads();
        if (t == 0) {
            const int old = atomicAdd(&g_doneB, 1);   // ATOM w/ return (32 only)
            if (old == 31) {                          // last B block: fan out
                __threadfence();
#pragma unroll
                for (int j = 0; j < 8; ++j)
                    asm volatile("st.release.gpu.b32 [%0], %1;"
                                 :: "l"(g_flagB + j * 32), "r"(1));
            }
        }

    } else {
        // ---- Phase C: gather 32 rows per block ---------------------------
        const int cb = b - 257;                  // 0..255

        // prefetch row patterns BEFORE waiting on B
        if (t < 32) {
            const int4* d4 = reinterpret_cast<const int4*>(data + (cb * 32 + t) * 8);
            int4 a = d4[0], c = d4[1];
            shp[t] = a.x | (a.y << 1) | (a.z << 2) | (a.w << 3)
                   | (c.x << 4) | (c.y << 5) | (c.z << 6) | (c.w << 7);
        }
        __syncthreads();

        if (t == 0) {                            // <=32 pollers per flag line
            const int* f = g_flagB + (cb & 7) * 32;
            while (ld_acq(f) == 0) __nanosleep(256);
        }
        __syncthreads();

        const float4* T4 = reinterpret_cast<const float4*>(g_T);
#pragma unroll
        for (int j = 0; j < 2; ++j) {
            const int gid = t + j * 256;         // 32 rows x 16 q
            const int r = gid >> 4, q = gid & 15;
            out[(size_t)(cb * 32 + r) * 16 + q] = T4[shp[r] * 16 + q];
        }

        // ---- epilogue: counter/flag reset for next replay ----------------
        __syncthreads();
        if (t == 0) {
            const int old = atomicAdd(&g_doneC, 1);
            if (old == 255) {                    // everyone past their spins
                g_doneC = 0;
                g_doneB = 0;
                g_doneA = 0;
#pragma unroll
                for (int j = 0; j < 8; ++j) g_flagB[j * 32] = 0;
            }
        }
    }
}

extern "C" void kernel_launch(void* const* d_in, const int* in_sizes, int n_in,
                              void* d_out, int out_size) {
    const int*   data      = (const int*)d_in[0];    // (8192, 8) int32
    const float* embedding = (const float*)d_in[1];  // (8, 2, 16)
    const float* head_w    = (const float*)d_in[2];  // (32, 32)
    const float* body_w    = (const float*)d_in[3];  // (7, 32, 32, 32)
    float* out = (float*)d_out;                      // (8192, 2, 32)

    fused_kernel<<<513, 256>>>(data, embedding, head_w, body_w, (float4*)out);
}

// round 9
// speedup vs baseline: 1.3851x; 1.3851x over previous
#include <cuda_runtime.h>

// GrassmannNN: SITE=8, DIM=16, D=32, B=8192.
// Back to 3 kernels (graph edges are the cheapest barriers — in-kernel flag
// pipelines measured slower). A is now fully coalesced/parallel.
//   A: 225 blocks — build 28 16x16 layer matrices M + tanh(head) vectors
//   B: 256 pattern-warps — forward all 256 bit patterns -> 64-float table
//   C: 131072 threads — per-row gather of the pattern outputs

#define NPAT 256

__device__ float g_M[7 * 2 * 2 * 256];          // [l][bit][s][i][k], sign folded
__device__ float g_h[32];                       // tanh(head) per bit
__device__ __align__(16) float g_T[NPAT * 64];  // pattern output table

// ---------------------------------------------------------------------------
// Kernel A: blocks 0..223 -> one (l, ig) slab of body_w each (coalesced 4KB
// load into smem, then 32 threads do the 16-length dots). Block 224 -> head.
// ---------------------------------------------------------------------------
__global__ void __launch_bounds__(256)
precompute_kernel(const float* __restrict__ emb,
                  const float* __restrict__ head_w,
                  const float* __restrict__ body_w) {
    __shared__ __align__(16) float sh[1024];
    const int b = blockIdx.x;
    const int t = threadIdx.x;

    if (b < 224) {
        const int l = b >> 5, ig = b & 31;
        reinterpret_cast<float4*>(sh)[t] =
            reinterpret_cast<const float4*>(body_w + (size_t)(l * 32 + ig) * 1024)[t];
        __syncthreads();
        if (t < 32) {
            const int bit = t >> 4, k = t & 15;
            const int s1 = ig >> 4, i = ig & 15;
            const int s = bit ? (1 - s1) : s1;
            const float* e = emb + ((l + 1) * 2 + bit) * 16;
            float acc = 0.f;
#pragma unroll
            for (int j = 0; j < 16; ++j)
                acc = fmaf(e[j], sh[(bit * 16 + j) * 32 + s * 16 + k], acc);
            if (bit == 1 && s == 0) acc = -acc;
            g_M[(((l * 2 + bit) * 2 + s) * 16 + i) * 16 + k] = acc;
        }
    } else if (t < 32) {
        const int bit = t >> 4, j = t & 15;
        const float* e = emb + bit * 16;                 // embedding[0][bit]
        float acc = 0.f;
#pragma unroll
        for (int k = 0; k < 16; ++k)
            acc = fmaf(e[k], head_w[(bit * 16 + k) * 32 + bit * 16 + j], acc);
        g_h[bit * 16 + j] = tanhf(acc);
    }
}

// ---------------------------------------------------------------------------
// Kernel B: one warp per pattern; lane (s,k) carries state u[s][k].
// Per-layer M coefficients double-buffered so only layer 0's load latency
// is exposed in the tanh dependency chain.
// ---------------------------------------------------------------------------
__global__ void __launch_bounds__(256)
pattern_kernel() {
    const int p = (blockIdx.x * blockDim.x + threadIdx.x) >> 5;
    const int lane = threadIdx.x & 31;
    if (p >= NPAT) return;
    const int s = lane >> 4, k = lane & 15;
    const int bit0 = p & 1;
    float u = (s == bit0) ? g_h[bit0 * 16 + k] : 0.f;

    float m[16];
    {
        const int bit = (p >> 1) & 1;
        const float* Mp = g_M + ((0 * 2 + bit) * 2 + s) * 256 + k;
#pragma unroll
        for (int i = 0; i < 16; ++i) m[i] = Mp[i * 16];
    }
#pragma unroll
    for (int l = 0; l < 7; ++l) {
        float m2[16];
        if (l < 6) {
            const int bitn = (p >> (l + 2)) & 1;
            const float* Mn = g_M + (((l + 1) * 2 + bitn) * 2 + s) * 256 + k;
#pragma unroll
            for (int i = 0; i < 16; ++i) m2[i] = Mn[i * 16];
        }
        const int bit = (p >> (l + 1)) & 1;
        const int src = (bit ? (1 - s) : s) << 4;
        float acc = 0.f;
#pragma unroll
        for (int i = 0; i < 16; ++i)
            acc = fmaf(__shfl_sync(0xffffffffu, u, src + i), m[i], acc);
        u = tanhf(acc);
#pragma unroll
        for (int i = 0; i < 16; ++i) m[i] = m2[i];
    }

    float* o = g_T + p * 64;
    o[48 * s + k] = u;               // live sector: offset s*32 + s*16 + k
    o[16 + 16 * s + k] = 0.f;        // structurally-zero sector
}

// ---------------------------------------------------------------------------
// Kernel C: gather — 16 threads per row copy its 64-float pattern output.
// ---------------------------------------------------------------------------
__global__ void __launch_bounds__(256)
gather_kernel(const int* __restrict__ data, float4* __restrict__ out) {
    const int tid = blockIdx.x * blockDim.x + threadIdx.x;  // 131072
    const int row = tid >> 4;
    const int q   = tid & 15;
    const int4* d4 = reinterpret_cast<const int4*>(data + (size_t)row * 8);
    const int4 a = __ldg(d4);
    const int4 c = __ldg(d4 + 1);
    const int p = a.x | (a.y << 1) | (a.z << 2) | (a.w << 3)
                | (c.x << 4) | (c.y << 5) | (c.z << 6) | (c.w << 7);
    out[tid] = __ldg(reinterpret_cast<const float4*>(g_T) + p * 16 + q);
}

extern "C" void kernel_launch(void* const* d_in, const int* in_sizes, int n_in,
                              void* d_out, int out_size) {
    const int*   data      = (const int*)d_in[0];    // (8192, 8) int32
    const float* embedding = (const float*)d_in[1];  // (8, 2, 16)
    const float* head_w    = (const float*)d_in[2];  // (32, 32)
    const float* body_w    = (const float*)d_in[3];  // (7, 32, 32, 32)
    float* out = (float*)d_out;                      // (8192, 2, 32)

    precompute_kernel<<<225, 256>>>(embedding, head_w, body_w);
    pattern_kernel<<<32, 256>>>();
    gather_kernel<<<512, 256>>>(data, (float4*)out);
}